// round 1
// baseline (speedup 1.0000x reference)
#include <cuda_runtime.h>

#define NCOL 2048
#define NROW 8192
#define THREADS 1024

// Scratch: per-row partial sums (device global; no allocation allowed).
__device__ float g_partial[NROW];

__global__ __launch_bounds__(THREADS, 2)
void sort_mse_kernel(const float* __restrict__ pred,
                     const float* __restrict__ tgt) {
    __shared__ float sp[NCOL];
    __shared__ float st[NCOL];
    __shared__ float swarp[32];

    const int row = blockIdx.x;
    const int tid = threadIdx.x;

    const float* __restrict__ p = pred + (size_t)row * NCOL;
    const float* __restrict__ t = tgt  + (size_t)row * NCOL;

    // Coalesced load of both rows into shared.
    sp[tid]        = p[tid];
    sp[tid + 1024] = p[tid + 1024];
    st[tid]        = t[tid];
    st[tid + 1024] = t[tid + 1024];
    __syncthreads();

    // Bitonic sort both arrays in lockstep (one barrier serves both).
    // 1024 comparators per pass, one per thread.
    #pragma unroll 1
    for (int k = 2; k <= NCOL; k <<= 1) {
        #pragma unroll 1
        for (int j = k >> 1; j > 0; j >>= 1) {
            const int i = ((tid & ~(j - 1)) << 1) | (tid & (j - 1));
            const int l = i | j;
            const bool up = ((i & k) == 0);

            float a = sp[i], b = sp[l];
            if ((a > b) == up) { sp[i] = b; sp[l] = a; }

            float c = st[i], d = st[l];
            if ((c > d) == up) { st[i] = d; st[l] = c; }

            __syncthreads();
        }
    }

    // Squared differences of matched (sorted) pairs.
    float d0 = sp[tid]        - st[tid];
    float d1 = sp[tid + 1024] - st[tid + 1024];
    float s  = d0 * d0 + d1 * d1;

    // Block reduction: warp shuffle, then cross-warp via shared.
    #pragma unroll
    for (int off = 16; off > 0; off >>= 1)
        s += __shfl_xor_sync(0xFFFFFFFFu, s, off);

    const int lane = tid & 31;
    const int wid  = tid >> 5;
    if (lane == 0) swarp[wid] = s;
    __syncthreads();

    if (wid == 0) {
        float v = swarp[lane];
        #pragma unroll
        for (int off = 16; off > 0; off >>= 1)
            v += __shfl_xor_sync(0xFFFFFFFFu, v, off);
        if (lane == 0) g_partial[row] = v;
    }
}

__global__ void final_reduce_kernel(float* __restrict__ out) {
    __shared__ float swarp[32];
    const int tid = threadIdx.x;

    float s = 0.0f;
    #pragma unroll
    for (int i = tid; i < NROW; i += THREADS)
        s += g_partial[i];

    #pragma unroll
    for (int off = 16; off > 0; off >>= 1)
        s += __shfl_xor_sync(0xFFFFFFFFu, s, off);

    const int lane = tid & 31;
    const int wid  = tid >> 5;
    if (lane == 0) swarp[wid] = s;
    __syncthreads();

    if (wid == 0) {
        float v = swarp[lane];
        #pragma unroll
        for (int off = 16; off > 0; off >>= 1)
            v += __shfl_xor_sync(0xFFFFFFFFu, v, off);
        if (lane == 0)
            out[0] = v * (1.0f / ((float)NROW * (float)NCOL));
    }
}

extern "C" void kernel_launch(void* const* d_in, const int* in_sizes, int n_in,
                              void* d_out, int out_size) {
    const float* pred = (const float*)d_in[0];
    const float* tgt  = (const float*)d_in[1];
    float* out = (float*)d_out;

    sort_mse_kernel<<<NROW, THREADS>>>(pred, tgt);
    final_reduce_kernel<<<1, THREADS>>>(out);
}

// round 2
// speedup vs baseline: 2.9562x; 2.9562x over previous
#include <cuda_runtime.h>

#define NCOL 2048
#define NROW 8192
#define T 256
#define V 8

__device__ float g_partial[NROW];

__device__ __forceinline__ void cswap(float& a, float& b, bool asc) {
    float lo = fminf(a, b), hi = fmaxf(a, b);
    a = asc ? lo : hi;
    b = asc ? hi : lo;
}

// Bitonic merge of 8 register elements (strides 4,2,1), uniform direction.
__device__ __forceinline__ void merge8(float v[V], bool asc) {
    cswap(v[0], v[4], asc); cswap(v[1], v[5], asc);
    cswap(v[2], v[6], asc); cswap(v[3], v[7], asc);
    cswap(v[0], v[2], asc); cswap(v[1], v[3], asc);
    cswap(v[4], v[6], asc); cswap(v[5], v[7], asc);
    cswap(v[0], v[1], asc); cswap(v[2], v[3], asc);
    cswap(v[4], v[5], asc); cswap(v[6], v[7], asc);
}

// Bitonic phases k=2,4 (fixed directions), then k=8 merge with direction asc8.
__device__ __forceinline__ void sort8_prefix(float v[V], bool asc8) {
    // k=2
    cswap(v[0], v[1], true);  cswap(v[2], v[3], false);
    cswap(v[4], v[5], true);  cswap(v[6], v[7], false);
    // k=4, j=2
    cswap(v[0], v[2], true);  cswap(v[1], v[3], true);
    cswap(v[4], v[6], false); cswap(v[5], v[7], false);
    // k=4, j=1
    cswap(v[0], v[1], true);  cswap(v[2], v[3], true);
    cswap(v[4], v[5], false); cswap(v[6], v[7], false);
    // k=8 (j=4,2,1)
    merge8(v, asc8);
}

__global__ __launch_bounds__(T)
void sort_mse_kernel(const float* __restrict__ pred,
                     const float* __restrict__ tgt) {
    __shared__ float bufp[2][NCOL];
    __shared__ float buft[2][NCOL];
    __shared__ float swarp[T / 32];

    const int row = blockIdx.x;
    const int tid = threadIdx.x;

    float vp[V], vt[V];

    // Coalesced vectorized load: thread owns elements [8*tid, 8*tid+7].
    {
        const float4* p4 = (const float4*)(pred + (size_t)row * NCOL) + tid * 2;
        const float4* t4 = (const float4*)(tgt  + (size_t)row * NCOL) + tid * 2;
        float4 a = p4[0], b = p4[1];
        vp[0] = a.x; vp[1] = a.y; vp[2] = a.z; vp[3] = a.w;
        vp[4] = b.x; vp[5] = b.y; vp[6] = b.z; vp[7] = b.w;
        float4 c = t4[0], d = t4[1];
        vt[0] = c.x; vt[1] = c.y; vt[2] = c.z; vt[3] = c.w;
        vt[4] = d.x; vt[5] = d.y; vt[6] = d.z; vt[7] = d.w;
    }

    // Phases k=2..8 entirely in registers. Direction for k=8: (i & 8)==0,
    // with i = 8*tid + e  ->  depends on tid bit 0.
    const bool asc8 = ((tid & 1) == 0);
    sort8_prefix(vp, asc8);
    sort8_prefix(vt, asc8);

    // Phases k=16..2048. km = k/8 (thread-level mask).
    int phase = 0;
    #pragma unroll 1
    for (int km = 2; km <= 256; km <<= 1) {
        const bool asc = ((tid & km) == 0);

        #pragma unroll 1
        for (int d = km >> 1; d >= 1; d >>= 1) {
            const bool keep_min = (((tid & d) == 0) == asc);

            if (d <= 16) {
                // Partner lane within warp: lane ^ d.
                #pragma unroll
                for (int e = 0; e < V; e++) {
                    float o = __shfl_xor_sync(0xFFFFFFFFu, vp[e], d);
                    vp[e] = keep_min ? fminf(vp[e], o) : fmaxf(vp[e], o);
                }
                #pragma unroll
                for (int e = 0; e < V; e++) {
                    float o = __shfl_xor_sync(0xFFFFFFFFu, vt[e], d);
                    vt[e] = keep_min ? fminf(vt[e], o) : fmaxf(vt[e], o);
                }
            } else {
                // Cross-warp exchange through shared (double-buffered, 1 barrier).
                float4* sp4 = (float4*)&bufp[phase][tid * V];
                float4* st4 = (float4*)&buft[phase][tid * V];
                sp4[0] = make_float4(vp[0], vp[1], vp[2], vp[3]);
                sp4[1] = make_float4(vp[4], vp[5], vp[6], vp[7]);
                st4[0] = make_float4(vt[0], vt[1], vt[2], vt[3]);
                st4[1] = make_float4(vt[4], vt[5], vt[6], vt[7]);
                __syncthreads();

                const int ptn = tid ^ d;
                const float4* pp4 = (const float4*)&bufp[phase][ptn * V];
                const float4* pt4 = (const float4*)&buft[phase][ptn * V];
                float4 oa = pp4[0], ob = pp4[1];
                float op[V] = {oa.x, oa.y, oa.z, oa.w, ob.x, ob.y, ob.z, ob.w};
                float4 oc = pt4[0], od = pt4[1];
                float ot[V] = {oc.x, oc.y, oc.z, oc.w, od.x, od.y, od.z, od.w};

                #pragma unroll
                for (int e = 0; e < V; e++) {
                    vp[e] = keep_min ? fminf(vp[e], op[e]) : fmaxf(vp[e], op[e]);
                    vt[e] = keep_min ? fminf(vt[e], ot[e]) : fmaxf(vt[e], ot[e]);
                }
                phase ^= 1;
            }
        }

        // In-thread tail (j=4,2,1), direction uniform per thread.
        merge8(vp, asc);
        merge8(vt, asc);
    }

    // Both arrays now sorted ascending; matched pairs are same index.
    float s = 0.0f;
    #pragma unroll
    for (int e = 0; e < V; e++) {
        float d = vp[e] - vt[e];
        s = fmaf(d, d, s);
    }

    #pragma unroll
    for (int off = 16; off > 0; off >>= 1)
        s += __shfl_xor_sync(0xFFFFFFFFu, s, off);

    const int lane = tid & 31;
    const int wid  = tid >> 5;
    if (lane == 0) swarp[wid] = s;
    __syncthreads();

    if (wid == 0) {
        float v = (lane < T / 32) ? swarp[lane] : 0.0f;
        #pragma unroll
        for (int off = 4; off > 0; off >>= 1)
            v += __shfl_xor_sync(0xFFFFFFFFu, v, off);
        if (lane == 0) g_partial[row] = v;
    }
}

__global__ void final_reduce_kernel(float* __restrict__ out) {
    __shared__ float swarp[32];
    const int tid = threadIdx.x;

    float s = 0.0f;
    #pragma unroll
    for (int i = tid; i < NROW; i += 1024)
        s += g_partial[i];

    #pragma unroll
    for (int off = 16; off > 0; off >>= 1)
        s += __shfl_xor_sync(0xFFFFFFFFu, s, off);

    const int lane = tid & 31;
    const int wid  = tid >> 5;
    if (lane == 0) swarp[wid] = s;
    __syncthreads();

    if (wid == 0) {
        float v = swarp[lane];
        #pragma unroll
        for (int off = 16; off > 0; off >>= 1)
            v += __shfl_xor_sync(0xFFFFFFFFu, v, off);
        if (lane == 0)
            out[0] = v * (1.0f / ((float)NROW * (float)NCOL));
    }
}

extern "C" void kernel_launch(void* const* d_in, const int* in_sizes, int n_in,
                              void* d_out, int out_size) {
    const float* pred = (const float*)d_in[0];
    const float* tgt  = (const float*)d_in[1];
    float* out = (float*)d_out;

    sort_mse_kernel<<<NROW, T>>>(pred, tgt);
    final_reduce_kernel<<<1, 1024>>>(out);
}

// round 3
// speedup vs baseline: 3.5838x; 1.2123x over previous
#include <cuda_runtime.h>

#define NCOL 2048
#define NROW 8192
#define T 256
#define V 8

__device__ float g_partial[NROW];

__device__ __forceinline__ void cswap_asc(float& a, float& b) {
    float lo = fminf(a, b);
    float hi = fmaxf(a, b);
    a = lo; b = hi;
}

__device__ __forceinline__ void cswap_desc(float& a, float& b) {
    float lo = fminf(a, b);
    float hi = fmaxf(a, b);
    a = hi; b = lo;
}

// Ascending bitonic merge of 8 register elements (strides 4,2,1).
__device__ __forceinline__ void merge8_asc(float v[V]) {
    cswap_asc(v[0], v[4]); cswap_asc(v[1], v[5]);
    cswap_asc(v[2], v[6]); cswap_asc(v[3], v[7]);
    cswap_asc(v[0], v[2]); cswap_asc(v[1], v[3]);
    cswap_asc(v[4], v[6]); cswap_asc(v[5], v[7]);
    cswap_asc(v[0], v[1]); cswap_asc(v[2], v[3]);
    cswap_asc(v[4], v[5]); cswap_asc(v[6], v[7]);
}

// Bitonic phases k=2,4 on element index i=8*tid+e: directions are
// compile-time ((i&2), (i&4)).
__device__ __forceinline__ void sort8_pre(float v[V]) {
    // k=2
    cswap_asc (v[0], v[1]); cswap_desc(v[2], v[3]);
    cswap_asc (v[4], v[5]); cswap_desc(v[6], v[7]);
    // k=4, j=2
    cswap_asc (v[0], v[2]); cswap_asc (v[1], v[3]);
    cswap_desc(v[4], v[6]); cswap_desc(v[5], v[7]);
    // k=4, j=1
    cswap_asc (v[0], v[1]); cswap_asc (v[2], v[3]);
    cswap_desc(v[4], v[5]); cswap_desc(v[6], v[7]);
}

// Sign-space transition into phase KM: flip sign iff the direction bit
// changed vs the previous phase (KM/2). FMULs go to the fma pipe (idle).
template<int KM>
__device__ __forceinline__ void flip_into(float yp[V], float yt[V], const int tid) {
    const bool flip = (((tid & KM) != 0) != ((tid & (KM >> 1)) != 0));
    const float s = flip ? -1.0f : 1.0f;
    #pragma unroll
    for (int e = 0; e < V; e++) { yp[e] *= s; yt[e] *= s; }
}

// One bitonic phase (element k = 8*KM) entirely in ascending sign-space.
// Thread-level strides d = KM/2..1; d>=32 via smem (double-buffered,
// 1 barrier per pass), d<=16 via warp shuffle. Tail strides 4,2,1 in regs.
template<int KM>
__device__ __forceinline__ void phase(float yp[V], float yt[V], const int tid,
                                      float (&bufp)[2][NCOL], float (&buft)[2][NCOL],
                                      int& ph) {
    #pragma unroll
    for (int d = KM / 2; d >= 1; d >>= 1) {
        const bool keep_lo = ((tid & d) == 0);
        if (d >= 32) {
            float4* sp4 = (float4*)&bufp[ph][tid * V];
            float4* st4 = (float4*)&buft[ph][tid * V];
            sp4[0] = make_float4(yp[0], yp[1], yp[2], yp[3]);
            sp4[1] = make_float4(yp[4], yp[5], yp[6], yp[7]);
            st4[0] = make_float4(yt[0], yt[1], yt[2], yt[3]);
            st4[1] = make_float4(yt[4], yt[5], yt[6], yt[7]);
            __syncthreads();

            const int ptn = tid ^ d;
            const float4* pp4 = (const float4*)&bufp[ph][ptn * V];
            const float4* pt4 = (const float4*)&buft[ph][ptn * V];
            float4 oa = pp4[0], ob = pp4[1];
            float4 oc = pt4[0], od = pt4[1];
            float op[V] = {oa.x, oa.y, oa.z, oa.w, ob.x, ob.y, ob.z, ob.w};
            float ot[V] = {oc.x, oc.y, oc.z, oc.w, od.x, od.y, od.z, od.w};

            #pragma unroll
            for (int e = 0; e < V; e++) {
                yp[e] = keep_lo ? fminf(yp[e], op[e]) : fmaxf(yp[e], op[e]);
                yt[e] = keep_lo ? fminf(yt[e], ot[e]) : fmaxf(yt[e], ot[e]);
            }
            ph ^= 1;
        } else {
            #pragma unroll
            for (int e = 0; e < V; e++) {
                float o1 = __shfl_xor_sync(0xFFFFFFFFu, yp[e], d);
                float o2 = __shfl_xor_sync(0xFFFFFFFFu, yt[e], d);
                yp[e] = keep_lo ? fminf(yp[e], o1) : fmaxf(yp[e], o1);
                yt[e] = keep_lo ? fminf(yt[e], o2) : fmaxf(yt[e], o2);
            }
        }
    }
    merge8_asc(yp);
    merge8_asc(yt);
}

__global__ __launch_bounds__(T)
void sort_mse_kernel(const float* __restrict__ pred,
                     const float* __restrict__ tgt) {
    __shared__ float bufp[2][NCOL];
    __shared__ float buft[2][NCOL];
    __shared__ float swarp[T / 32];

    const int row = blockIdx.x;
    const int tid = threadIdx.x;

    float yp[V], yt[V];

    // Coalesced vectorized load: thread owns elements [8*tid, 8*tid+7].
    {
        const float4* p4 = (const float4*)(pred + (size_t)row * NCOL) + tid * 2;
        const float4* t4 = (const float4*)(tgt  + (size_t)row * NCOL) + tid * 2;
        float4 a = p4[0], b = p4[1];
        yp[0] = a.x; yp[1] = a.y; yp[2] = a.z; yp[3] = a.w;
        yp[4] = b.x; yp[5] = b.y; yp[6] = b.z; yp[7] = b.w;
        float4 c = t4[0], d = t4[1];
        yt[0] = c.x; yt[1] = c.y; yt[2] = c.z; yt[3] = c.w;
        yt[4] = d.x; yt[5] = d.y; yt[6] = d.z; yt[7] = d.w;
    }

    // k=2,4: compile-time directions in natural space.
    sort8_pre(yp);
    sort8_pre(yt);

    // Enter sign space for k=8: descending iff (tid & 1).
    {
        const float s = (tid & 1) ? -1.0f : 1.0f;
        #pragma unroll
        for (int e = 0; e < V; e++) { yp[e] *= s; yt[e] *= s; }
    }
    merge8_asc(yp);
    merge8_asc(yt);

    int ph = 0;
    flip_into<2>(yp, yt, tid);   phase<2>(yp, yt, tid, bufp, buft, ph);
    flip_into<4>(yp, yt, tid);   phase<4>(yp, yt, tid, bufp, buft, ph);
    flip_into<8>(yp, yt, tid);   phase<8>(yp, yt, tid, bufp, buft, ph);
    flip_into<16>(yp, yt, tid);  phase<16>(yp, yt, tid, bufp, buft, ph);
    flip_into<32>(yp, yt, tid);  phase<32>(yp, yt, tid, bufp, buft, ph);
    flip_into<64>(yp, yt, tid);  phase<64>(yp, yt, tid, bufp, buft, ph);
    flip_into<128>(yp, yt, tid); phase<128>(yp, yt, tid, bufp, buft, ph);
    flip_into<256>(yp, yt, tid); phase<256>(yp, yt, tid, bufp, buft, ph);
    // Last phase (k=2048) is ascending for all tid<256 -> final space is
    // the natural one; yp/yt are the sorted rows.

    float s = 0.0f;
    #pragma unroll
    for (int e = 0; e < V; e++) {
        float d = yp[e] - yt[e];
        s = fmaf(d, d, s);
    }

    #pragma unroll
    for (int off = 16; off > 0; off >>= 1)
        s += __shfl_xor_sync(0xFFFFFFFFu, s, off);

    const int lane = tid & 31;
    const int wid  = tid >> 5;
    if (lane == 0) swarp[wid] = s;
    __syncthreads();

    if (wid == 0) {
        float v = (lane < T / 32) ? swarp[lane] : 0.0f;
        #pragma unroll
        for (int off = 4; off > 0; off >>= 1)
            v += __shfl_xor_sync(0xFFFFFFFFu, v, off);
        if (lane == 0) g_partial[row] = v;
    }
}

__global__ void final_reduce_kernel(float* __restrict__ out) {
    __shared__ float swarp[32];
    const int tid = threadIdx.x;

    float s = 0.0f;
    #pragma unroll
    for (int i = tid; i < NROW; i += 1024)
        s += g_partial[i];

    #pragma unroll
    for (int off = 16; off > 0; off >>= 1)
        s += __shfl_xor_sync(0xFFFFFFFFu, s, off);

    const int lane = tid & 31;
    const int wid  = tid >> 5;
    if (lane == 0) swarp[wid] = s;
    __syncthreads();

    if (wid == 0) {
        float v = swarp[lane];
        #pragma unroll
        for (int off = 16; off > 0; off >>= 1)
            v += __shfl_xor_sync(0xFFFFFFFFu, v, off);
        if (lane == 0)
            out[0] = v * (1.0f / ((float)NROW * (float)NCOL));
    }
}

extern "C" void kernel_launch(void* const* d_in, const int* in_sizes, int n_in,
                              void* d_out, int out_size) {
    const float* pred = (const float*)d_in[0];
    const float* tgt  = (const float*)d_in[1];
    float* out = (float*)d_out;

    sort_mse_kernel<<<NROW, T>>>(pred, tgt);
    final_reduce_kernel<<<1, 1024>>>(out);
}